// round 3
// baseline (speedup 1.0000x reference)
#include <cuda_runtime.h>
#include <math.h>

#define G_GROUPS 256
#define TRAJ 8
#define EVALN 30
#define NPTS 240          /* TRAJ*EVALN */
#define NX 400
#define NY 400
#define NZ 64

__device__ float g_pos[G_GROUPS * NPTS * 3];
__device__ int   g_mn[G_GROUPS * 3];
__device__ int   g_ls[G_GROUPS * 3];   // K1: mx ; K2 overwrites with lshape

// ---------------------------------------------------------------------------
// K1: coefficients -> positions -> per-group voxel bbox (mn/mx ints)
// ---------------------------------------------------------------------------
__global__ __launch_bounds__(256) void k_pos(
    const float* __restrict__ Df, const float* __restrict__ Dp,
    const float* __restrict__ L, const float* __restrict__ minb,
    const int* __restrict__ map_id)
{
    int g = blockIdx.x;
    int tid = threadIdx.x;

    __shared__ float s_L[36];
    __shared__ float s_coe[TRAJ][3][6];
    __shared__ float smin[3][256];
    __shared__ float smax[3][256];

    if (tid < 36) s_L[tid] = L[tid];
    __syncthreads();

    // 144 (traj,dim,j) coefficient entries
    if (tid < 144) {
        int traj = tid / 18;
        int rem  = tid % 18;
        int dim  = rem / 6;
        int j    = rem % 6;
        int b = g * TRAJ + traj;
        const float* df = Df + (b * 3 + dim) * 3;
        const float* dp = Dp + (b * 3 + dim) * 3;
        float dv[6];
        dv[0] = df[0]; dv[1] = df[1]; dv[2] = df[2];
        dv[3] = dp[0]; dv[4] = dp[1]; dv[5] = dp[2];
        float c = 0.0f;
        #pragma unroll
        for (int k = 0; k < 6; ++k) c += s_L[j * 6 + k] * dv[k];
        s_coe[traj][dim][j] = c;
    }
    __syncthreads();

    float pv[3];
    bool act = (tid < NPTS);
    if (act) {
        int traj = tid / EVALN;
        int n    = tid % EVALN;
        double dtd  = 2.0 / 30.0;
        double stpd = (2.0 - dtd) / 29.0;
        float t = (float)(dtd + (double)n * stpd);
        float tp[6];
        tp[0] = 1.0f;
        #pragma unroll
        for (int k = 1; k < 6; ++k) tp[k] = tp[k - 1] * t;
        #pragma unroll
        for (int d = 0; d < 3; ++d) {
            float p = 0.0f;
            #pragma unroll
            for (int k = 0; k < 6; ++k) p += tp[k] * s_coe[traj][d][k];
            pv[d] = p;
            g_pos[(g * NPTS + tid) * 3 + d] = p;
        }
    }
    #pragma unroll
    for (int d = 0; d < 3; ++d) {
        smin[d][tid] = act ? pv[d] :  3.0e38f;
        smax[d][tid] = act ? pv[d] : -3.0e38f;
    }
    __syncthreads();
    for (int s = 128; s > 0; s >>= 1) {
        if (tid < s) {
            #pragma unroll
            for (int d = 0; d < 3; ++d) {
                smin[d][tid] = fminf(smin[d][tid], smin[d][tid + s]);
                smax[d][tid] = fmaxf(smax[d][tid], smax[d][tid + s]);
            }
        }
        __syncthreads();
    }
    if (tid == 0) {
        int m = map_id[g];
        #pragma unroll
        for (int d = 0; d < 3; ++d) {
            float mb = minb[m * 3 + d];
            // (int) cast == trunc-toward-zero, matching jnp.trunc().astype(int32)
            g_mn[g * 3 + d] = (int)((smin[d][0] - mb) / 0.2f);
            g_ls[g * 3 + d] = (int)((smax[d][0] - mb) / 0.2f);
        }
    }
}

// ---------------------------------------------------------------------------
// K2: cross-group max_spans + clamp cascade + cross-group shift (one block)
// ---------------------------------------------------------------------------
__global__ __launch_bounds__(256) void k_box(
    const float* __restrict__ shapes, const int* __restrict__ map_id)
{
    int g = threadIdx.x;  // 256 groups, one thread each
    __shared__ int red[3][256];

    int mn[3], mx[3];
    #pragma unroll
    for (int d = 0; d < 3; ++d) {
        mn[d] = g_mn[g * 3 + d];
        mx[d] = g_ls[g * 3 + d];
        red[d][g] = mx[d] - mn[d];
    }
    __syncthreads();
    for (int s = 128; s > 0; s >>= 1) {
        if (g < s) {
            #pragma unroll
            for (int d = 0; d < 3; ++d)
                red[d][g] = max(red[d][g], red[d][g + s]);
        }
        __syncthreads();
    }
    int ms[3];
    #pragma unroll
    for (int d = 0; d < 3; ++d) ms[d] = red[d][0];
    __syncthreads();

    int m = map_id[g];
    int mn2[3], mx2[3];
    #pragma unroll
    for (int d = 0; d < 3; ++d) {
        int shp = (int)shapes[m * 3 + d];
        int c = (mn[d] + mx[d]) >> 1;      // floor div (arith shift)
        int a = c - (ms[d] >> 1) - 5;      // ms >= 0
        int b = c + (ms[d] >> 1) + 5;
        int nmn = a > 0 ? a : 0;
        b += (nmn - a); a = nmn;
        int nmx = b < shp ? b : shp;
        a -= (b - nmx); b = nmx;
        mn2[d] = a; mx2[d] = b;
        red[d][g] = (a < 0) ? -a : 0;      // shift contribution
    }
    __syncthreads();
    for (int s = 128; s > 0; s >>= 1) {
        if (g < s) {
            #pragma unroll
            for (int d = 0; d < 3; ++d)
                red[d][g] = max(red[d][g], red[d][g + s]);
        }
        __syncthreads();
    }
    #pragma unroll
    for (int d = 0; d < 3; ++d) {
        int sh = red[d][0];
        g_mn[g * 3 + d] = mn2[d] + sh;
        g_ls[g * 3 + d] = mx2[d] - mn2[d] - sh;  // lshape = mx - (mn + shift)
    }
}

// ---------------------------------------------------------------------------
// K3: trilinear SDF gather + exp cost + per-trajectory sums
// ---------------------------------------------------------------------------
__global__ __launch_bounds__(256) void k_cost(
    const float* __restrict__ sdf, const float* __restrict__ minb,
    const int* __restrict__ map_id, float* __restrict__ out)
{
    int g = blockIdx.x;
    int tid = threadIdx.x;

    __shared__ int s_mn[3], s_ls[3];
    __shared__ float s_lo[3];
    __shared__ int s_m;
    __shared__ float s_cost[NPTS];

    if (tid == 0) s_m = map_id[g];
    if (tid < 3) {
        int mnv = g_mn[g * 3 + tid];
        s_mn[tid] = mnv;
        s_ls[tid] = g_ls[g * 3 + tid];
        s_lo[tid] = (float)mnv * 0.2f + minb[map_id[g] * 3 + tid];
    }
    __syncthreads();

    if (tid < NPTS) {
        const float* pp = g_pos + (g * NPTS + tid) * 3;
        float fr[3];
        int l0[3];
        bool valid = true;
        #pragma unroll
        for (int d = 0; d < 3; ++d) {
            float grid = (pp[d] - s_lo[d]) / 0.2f;
            float gp = 2.0f * grid / (float)(s_ls[d] - 1) - 1.0f;
            valid = valid && (gp < 0.99f) && (gp > -0.99f);
            float fl = floorf(grid);
            l0[d] = (int)fl;
            fr[d] = grid - fl;
        }

        const float* mp = sdf + (size_t)s_m * (NZ * NY * NX);
        float acc = 0.0f;
        #pragma unroll
        for (int dx = 0; dx < 2; ++dx)
        #pragma unroll
        for (int dy = 0; dy < 2; ++dy)
        #pragma unroll
        for (int dz = 0; dz < 2; ++dz) {
            int ix = l0[0] + dx, iy = l0[1] + dy, iz = l0[2] + dz;
            bool inb = (ix >= 0) && (ix < s_ls[0]) &&
                       (iy >= 0) && (iy < s_ls[1]) &&
                       (iz >= 0) && (iz < s_ls[2]);
            if (inb) {
                int gx = min(max(ix + s_mn[0], 0), NX - 1);
                int gy = min(max(iy + s_mn[1], 0), NY - 1);
                int gz = min(max(iz + s_mn[2], 0), NZ - 1);
                float val = __ldg(mp + ((size_t)gz * NY + gy) * NX + gx);
                float w = (dx ? fr[0] : 1.0f - fr[0]) *
                          (dy ? fr[1] : 1.0f - fr[1]) *
                          (dz ? fr[2] : 1.0f - fr[2]);
                acc += w * val;
            }
        }
        float cost = valid ? expf((-(acc - 0.5f)) / 0.3f) : 0.0f;
        const float dtf = (float)(2.0 / 30.0);
        s_cost[tid] = cost * dtf;
    }
    __syncthreads();

    if (tid < TRAJ) {
        float s = 0.0f;
        #pragma unroll
        for (int n = 0; n < EVALN; ++n)
            s += s_cost[tid * EVALN + n];
        out[g * TRAJ + tid] = s;
    }
}

// ---------------------------------------------------------------------------
extern "C" void kernel_launch(void* const* d_in, const int* in_sizes, int n_in,
                              void* d_out, int out_size)
{
    const float* Df     = (const float*)d_in[0];
    const float* Dp     = (const float*)d_in[1];
    const float* L      = (const float*)d_in[2];
    const float* sdf    = (const float*)d_in[3];
    const float* minb   = (const float*)d_in[4];
    const float* shapes = (const float*)d_in[5];
    const int*   map_id = (const int*)d_in[6];
    float* out = (float*)d_out;

    k_pos <<<G_GROUPS, 256>>>(Df, Dp, L, minb, map_id);
    k_box <<<1, 256>>>(shapes, map_id);
    k_cost<<<G_GROUPS, 256>>>(sdf, minb, map_id, out);
}

// round 4
// speedup vs baseline: 1.1830x; 1.1830x over previous
#include <cuda_runtime.h>
#include <math.h>

#define G_GROUPS 256
#define TRAJ 8
#define EVALN 30
#define NPTS 240          /* TRAJ*EVALN */
#define NX 400
#define NY 400
#define NZ 64
#define FULLMASK 0xffffffffu

__device__ int      g_mn[G_GROUPS * 3];
__device__ int      g_mx[G_GROUPS * 3];
__device__ unsigned g_cnt;   // monotonic grid-barrier counter (never reset)

__global__ __launch_bounds__(256) void k_fused(
    const float* __restrict__ Df, const float* __restrict__ Dp,
    const float* __restrict__ L,  const float* __restrict__ sdf,
    const float* __restrict__ minb, const float* __restrict__ shapes,
    const int* __restrict__ map_id, float* __restrict__ out)
{
    int g    = blockIdx.x;
    int tid  = threadIdx.x;
    int lane = tid & 31;
    int wid  = tid >> 5;

    __shared__ float s_L[36];
    __shared__ float s_coe[TRAJ][3][6];
    __shared__ float s_wmin[3][8], s_wmax[3][8];
    __shared__ int   s_ired[3][8];
    __shared__ int   s_gmn[3], s_gls[3];
    __shared__ float s_lo[3];
    __shared__ int   s_m;
    __shared__ float s_cost[NPTS];

    // ---------------- Phase A: coefficients -> positions (registers) -------
    if (tid < 36) s_L[tid] = L[tid];
    __syncthreads();

    if (tid < 144) {
        int traj = tid / 18;
        int rem  = tid % 18;
        int dim  = rem / 6;
        int j    = rem % 6;
        int b = g * TRAJ + traj;
        const float* df = Df + (b * 3 + dim) * 3;
        const float* dp = Dp + (b * 3 + dim) * 3;
        float dv[6];
        dv[0] = df[0]; dv[1] = df[1]; dv[2] = df[2];
        dv[3] = dp[0]; dv[4] = dp[1]; dv[5] = dp[2];
        float c = 0.0f;
        #pragma unroll
        for (int k = 0; k < 6; ++k) c += s_L[j * 6 + k] * dv[k];
        s_coe[traj][dim][j] = c;
    }
    __syncthreads();

    float pv[3];
    bool act = (tid < NPTS);
    if (act) {
        int traj = tid / EVALN;
        int n    = tid % EVALN;
        double dtd  = 2.0 / 30.0;
        double stpd = (2.0 - dtd) / 29.0;
        float t = (float)(dtd + (double)n * stpd);
        float tp[6];
        tp[0] = 1.0f;
        #pragma unroll
        for (int k = 1; k < 6; ++k) tp[k] = tp[k - 1] * t;
        #pragma unroll
        for (int d = 0; d < 3; ++d) {
            float p = 0.0f;
            #pragma unroll
            for (int k = 0; k < 6; ++k) p += tp[k] * s_coe[traj][d][k];
            pv[d] = p;
        }
    }

    // ---------------- per-group bbox via warp shuffles ----------------------
    float mn3[3], mx3[3];
    #pragma unroll
    for (int d = 0; d < 3; ++d) {
        mn3[d] = act ? pv[d] :  3.0e38f;
        mx3[d] = act ? pv[d] : -3.0e38f;
    }
    #pragma unroll
    for (int off = 16; off > 0; off >>= 1) {
        #pragma unroll
        for (int d = 0; d < 3; ++d) {
            mn3[d] = fminf(mn3[d], __shfl_xor_sync(FULLMASK, mn3[d], off));
            mx3[d] = fmaxf(mx3[d], __shfl_xor_sync(FULLMASK, mx3[d], off));
        }
    }
    if (lane == 0) {
        #pragma unroll
        for (int d = 0; d < 3; ++d) { s_wmin[d][wid] = mn3[d]; s_wmax[d][wid] = mx3[d]; }
    }
    __syncthreads();

    // ---------------- publish mn/mx + software grid barrier -----------------
    if (tid == 0) {
        int m = map_id[g];
        #pragma unroll
        for (int d = 0; d < 3; ++d) {
            float a = s_wmin[d][0], b = s_wmax[d][0];
            #pragma unroll
            for (int w = 1; w < 8; ++w) {
                a = fminf(a, s_wmin[d][w]);
                b = fmaxf(b, s_wmax[d][w]);
            }
            float mb = minb[m * 3 + d];
            // (int) cast == trunc-toward-zero == jnp.trunc().astype(int32)
            g_mn[g * 3 + d] = (int)((a - mb) / 0.2f);
            g_mx[g * 3 + d] = (int)((b - mb) / 0.2f);
        }
        __threadfence();
        unsigned arrive = atomicAdd(&g_cnt, 1u) + 1u;
        unsigned target = (arrive + (unsigned)(G_GROUPS - 1)) & ~(unsigned)(G_GROUPS - 1);
        volatile unsigned* pc = &g_cnt;
        while (*pc < target) { }
        __threadfence();
    }
    __syncthreads();

    // ---------------- Phase B: global max_spans + clamp + shift (redundant) -
    {
        int gg = tid;             // one group per thread
        int mnv[3], mxv[3], sp[3];
        #pragma unroll
        for (int d = 0; d < 3; ++d) {
            mnv[d] = g_mn[gg * 3 + d];
            mxv[d] = g_mx[gg * 3 + d];
            sp[d]  = mxv[d] - mnv[d];
        }
        #pragma unroll
        for (int off = 16; off > 0; off >>= 1)
            #pragma unroll
            for (int d = 0; d < 3; ++d)
                sp[d] = max(sp[d], __shfl_xor_sync(FULLMASK, sp[d], off));
        if (lane == 0) {
            #pragma unroll
            for (int d = 0; d < 3; ++d) s_ired[d][wid] = sp[d];
        }
        __syncthreads();
        int ms[3];
        #pragma unroll
        for (int d = 0; d < 3; ++d) {
            int v = s_ired[d][0];
            #pragma unroll
            for (int w = 1; w < 8; ++w) v = max(v, s_ired[d][w]);
            ms[d] = v;
        }
        __syncthreads();          // before reusing s_ired

        int m2 = map_id[gg];
        int mn2[3], mx2[3], shc[3];
        #pragma unroll
        for (int d = 0; d < 3; ++d) {
            int shp = (int)shapes[m2 * 3 + d];
            int c = (mnv[d] + mxv[d]) >> 1;   // floor div (arith shift)
            int a = c - (ms[d] >> 1) - 5;     // ms >= 0
            int b = c + (ms[d] >> 1) + 5;
            int nmn = a > 0 ? a : 0;
            b += (nmn - a); a = nmn;
            int nmx = b < shp ? b : shp;
            a -= (b - nmx); b = nmx;
            mn2[d] = a; mx2[d] = b;
            shc[d] = (a < 0) ? -a : 0;
        }
        #pragma unroll
        for (int off = 16; off > 0; off >>= 1)
            #pragma unroll
            for (int d = 0; d < 3; ++d)
                shc[d] = max(shc[d], __shfl_xor_sync(FULLMASK, shc[d], off));
        if (lane == 0) {
            #pragma unroll
            for (int d = 0; d < 3; ++d) s_ired[d][wid] = shc[d];
        }
        __syncthreads();
        if (tid == g) {           // this thread computed OUR group's clamp
            #pragma unroll
            for (int d = 0; d < 3; ++d) {
                int v = s_ired[d][0];
                #pragma unroll
                for (int w = 1; w < 8; ++w) v = max(v, s_ired[d][w]);
                int a = mn2[d] + v;
                s_gmn[d] = a;
                s_gls[d] = mx2[d] - a;
                s_lo[d]  = (float)a * 0.2f + minb[m2 * 3 + d];
            }
            s_m = m2;
        }
        __syncthreads();
    }

    // ---------------- Phase C: trilinear gather + exp cost ------------------
    if (act) {
        float fr[3];
        int l0[3];
        bool valid = true;
        #pragma unroll
        for (int d = 0; d < 3; ++d) {
            float grid = (pv[d] - s_lo[d]) / 0.2f;
            float gp = 2.0f * grid / (float)(s_gls[d] - 1) - 1.0f;
            valid = valid && (gp < 0.99f) && (gp > -0.99f);
            float fl = floorf(grid);
            l0[d] = (int)fl;
            fr[d] = grid - fl;
        }

        const float* mp = sdf + (size_t)s_m * (NZ * NY * NX);
        float acc = 0.0f;
        #pragma unroll
        for (int dx = 0; dx < 2; ++dx)
        #pragma unroll
        for (int dy = 0; dy < 2; ++dy)
        #pragma unroll
        for (int dz = 0; dz < 2; ++dz) {
            int ix = l0[0] + dx, iy = l0[1] + dy, iz = l0[2] + dz;
            bool inb = (ix >= 0) && (ix < s_gls[0]) &&
                       (iy >= 0) && (iy < s_gls[1]) &&
                       (iz >= 0) && (iz < s_gls[2]);
            if (inb) {
                int gx = min(max(ix + s_gmn[0], 0), NX - 1);
                int gy = min(max(iy + s_gmn[1], 0), NY - 1);
                int gz = min(max(iz + s_gmn[2], 0), NZ - 1);
                float val = __ldg(mp + ((size_t)gz * NY + gy) * NX + gx);
                float w = (dx ? fr[0] : 1.0f - fr[0]) *
                          (dy ? fr[1] : 1.0f - fr[1]) *
                          (dz ? fr[2] : 1.0f - fr[2]);
                acc += w * val;
            }
        }
        float cost = valid ? expf((-(acc - 0.5f)) / 0.3f) : 0.0f;
        const float dtf = (float)(2.0 / 30.0);
        s_cost[tid] = cost * dtf;
    }
    __syncthreads();

    if (tid < TRAJ) {
        float s = 0.0f;
        #pragma unroll
        for (int n = 0; n < EVALN; ++n)
            s += s_cost[tid * EVALN + n];
        out[g * TRAJ + tid] = s;
    }
}

// ---------------------------------------------------------------------------
extern "C" void kernel_launch(void* const* d_in, const int* in_sizes, int n_in,
                              void* d_out, int out_size)
{
    const float* Df     = (const float*)d_in[0];
    const float* Dp     = (const float*)d_in[1];
    const float* L      = (const float*)d_in[2];
    const float* sdf    = (const float*)d_in[3];
    const float* minb   = (const float*)d_in[4];
    const float* shapes = (const float*)d_in[5];
    const int*   map_id = (const int*)d_in[6];
    float* out = (float*)d_out;

    k_fused<<<G_GROUPS, 256>>>(Df, Dp, L, sdf, minb, shapes, map_id, out);
}

// round 5
// speedup vs baseline: 1.2520x; 1.0584x over previous
#include <cuda_runtime.h>
#include <math.h>

#define G_GROUPS 256
#define TRAJ 8
#define EVALN 30
#define NPTS 240          /* TRAJ*EVALN */
#define NX 400
#define NY 400
#define NZ 64
#define FULLMASK 0xffffffffu

__device__ int4     g_bmn[G_GROUPS];   // .xyz = voxel mn, .w unused
__device__ int4     g_bmx[G_GROUPS];   // .xyz = voxel mx, .w unused
__device__ unsigned g_cnt;             // monotonic grid-barrier counter

__global__ __launch_bounds__(256) void k_fused(
    const float* __restrict__ Df, const float* __restrict__ Dp,
    const float* __restrict__ L,  const float* __restrict__ sdf,
    const float* __restrict__ minb, const float* __restrict__ shapes,
    const int* __restrict__ map_id, float* __restrict__ out)
{
    int g    = blockIdx.x;
    int tid  = threadIdx.x;
    int lane = tid & 31;
    int wid  = tid >> 5;

    __shared__ float s_L[36];
    __shared__ float s_df[72], s_dp[72];
    __shared__ float s_coe[TRAJ][3][6];
    __shared__ float s_wmin[3][8], s_wmax[3][8];
    __shared__ int   s_ired[3][8];
    __shared__ int   s_gmn[3], s_gls[3];
    __shared__ float s_lo[3];
    __shared__ int   s_m;
    __shared__ float s_cost[NPTS];

    // ---------------- Phase A: coalesced input staging ----------------------
    if (tid < 36) s_L[tid] = L[tid];
    if (tid < 72)                s_df[tid]      = Df[g * 72 + tid];
    else if (tid < 144)          s_dp[tid - 72] = Dp[g * 72 + (tid - 72)];

    // Prefetch (latency hidden under barrier): own group's map + shapes/minb
    int pf_m   = map_id[tid];              // tid in [0,256) == group index gg
    int pf_shp[3]; float pf_mb[3];
    #pragma unroll
    for (int d = 0; d < 3; ++d) {
        pf_shp[d] = (int)shapes[pf_m * 3 + d];
        pf_mb[d]  = minb[pf_m * 3 + d];
    }
    __syncthreads();

    if (tid < 144) {
        int traj = tid / 18;
        int rem  = tid % 18;
        int dim  = rem / 6;
        int j    = rem % 6;
        float dv[6];
        #pragma unroll
        for (int k = 0; k < 3; ++k) {
            dv[k]     = s_df[traj * 9 + dim * 3 + k];
            dv[k + 3] = s_dp[traj * 9 + dim * 3 + k];
        }
        float c = 0.0f;
        #pragma unroll
        for (int k = 0; k < 6; ++k) c += s_L[j * 6 + k] * dv[k];
        s_coe[traj][dim][j] = c;
    }
    __syncthreads();

    float pv[3];
    bool act = (tid < NPTS);
    if (act) {
        int traj = tid / EVALN;
        int n    = tid % EVALN;
        double dtd  = 2.0 / 30.0;
        double stpd = (2.0 - dtd) / 29.0;
        float t = (float)(dtd + (double)n * stpd);
        float tp[6];
        tp[0] = 1.0f;
        #pragma unroll
        for (int k = 1; k < 6; ++k) tp[k] = tp[k - 1] * t;
        #pragma unroll
        for (int d = 0; d < 3; ++d) {
            float p = 0.0f;
            #pragma unroll
            for (int k = 0; k < 6; ++k) p += tp[k] * s_coe[traj][d][k];
            pv[d] = p;
        }
    }

    // ---------------- per-group bbox via warp shuffles ----------------------
    float mn3[3], mx3[3];
    #pragma unroll
    for (int d = 0; d < 3; ++d) {
        mn3[d] = act ? pv[d] :  3.0e38f;
        mx3[d] = act ? pv[d] : -3.0e38f;
    }
    #pragma unroll
    for (int off = 16; off > 0; off >>= 1) {
        #pragma unroll
        for (int d = 0; d < 3; ++d) {
            mn3[d] = fminf(mn3[d], __shfl_xor_sync(FULLMASK, mn3[d], off));
            mx3[d] = fmaxf(mx3[d], __shfl_xor_sync(FULLMASK, mx3[d], off));
        }
    }
    if (lane == 0) {
        #pragma unroll
        for (int d = 0; d < 3; ++d) { s_wmin[d][wid] = mn3[d]; s_wmax[d][wid] = mx3[d]; }
    }
    __syncthreads();

    // ---------------- publish packed box + software grid barrier ------------
    if (tid == 0) {
        int m = map_id[g];
        int mni[3], mxi[3];
        #pragma unroll
        for (int d = 0; d < 3; ++d) {
            float a = s_wmin[d][0], b = s_wmax[d][0];
            #pragma unroll
            for (int w = 1; w < 8; ++w) {
                a = fminf(a, s_wmin[d][w]);
                b = fmaxf(b, s_wmax[d][w]);
            }
            float mb = minb[m * 3 + d];
            // (int) cast == trunc-toward-zero == jnp.trunc().astype(int32)
            mni[d] = (int)((a - mb) / 0.2f);
            mxi[d] = (int)((b - mb) / 0.2f);
        }
        g_bmn[g] = make_int4(mni[0], mni[1], mni[2], 0);
        g_bmx[g] = make_int4(mxi[0], mxi[1], mxi[2], 0);
        __threadfence();
        unsigned arrive = atomicAdd(&g_cnt, 1u) + 1u;
        unsigned target = (arrive + (unsigned)(G_GROUPS - 1)) & ~(unsigned)(G_GROUPS - 1);
        volatile unsigned* pc = &g_cnt;
        while (*pc < target) { }
        __threadfence();
    }
    __syncthreads();

    // ---------------- Phase B: global max_spans + clamp + shift (redundant) -
    {
        int4 b4mn = g_bmn[tid];        // one group per thread, 2x LDG.128
        int4 b4mx = g_bmx[tid];
        int mnv[3] = { b4mn.x, b4mn.y, b4mn.z };
        int mxv[3] = { b4mx.x, b4mx.y, b4mx.z };
        int sp[3];
        #pragma unroll
        for (int d = 0; d < 3; ++d) sp[d] = mxv[d] - mnv[d];
        #pragma unroll
        for (int off = 16; off > 0; off >>= 1)
            #pragma unroll
            for (int d = 0; d < 3; ++d)
                sp[d] = max(sp[d], __shfl_xor_sync(FULLMASK, sp[d], off));
        if (lane == 0) {
            #pragma unroll
            for (int d = 0; d < 3; ++d) s_ired[d][wid] = sp[d];
        }
        __syncthreads();
        int ms[3];
        #pragma unroll
        for (int d = 0; d < 3; ++d) {
            int v = s_ired[d][0];
            #pragma unroll
            for (int w = 1; w < 8; ++w) v = max(v, s_ired[d][w]);
            ms[d] = v;
        }
        __syncthreads();          // before reusing s_ired

        int mn2[3], mx2[3], shc[3];
        #pragma unroll
        for (int d = 0; d < 3; ++d) {
            int c = (mnv[d] + mxv[d]) >> 1;   // floor div (arith shift)
            int a = c - (ms[d] >> 1) - 5;     // ms >= 0
            int b = c + (ms[d] >> 1) + 5;
            int nmn = a > 0 ? a : 0;
            b += (nmn - a); a = nmn;
            int nmx = b < pf_shp[d] ? b : pf_shp[d];
            a -= (b - nmx); b = nmx;
            mn2[d] = a; mx2[d] = b;
            shc[d] = (a < 0) ? -a : 0;
        }
        #pragma unroll
        for (int off = 16; off > 0; off >>= 1)
            #pragma unroll
            for (int d = 0; d < 3; ++d)
                shc[d] = max(shc[d], __shfl_xor_sync(FULLMASK, shc[d], off));
        if (lane == 0) {
            #pragma unroll
            for (int d = 0; d < 3; ++d) s_ired[d][wid] = shc[d];
        }
        __syncthreads();
        if (tid == g) {           // this thread computed OUR group's clamp
            #pragma unroll
            for (int d = 0; d < 3; ++d) {
                int v = s_ired[d][0];
                #pragma unroll
                for (int w = 1; w < 8; ++w) v = max(v, s_ired[d][w]);
                int a = mn2[d] + v;
                s_gmn[d] = a;
                s_gls[d] = mx2[d] - a;
                s_lo[d]  = (float)a * 0.2f + pf_mb[d];
            }
            s_m = pf_m;
        }
        __syncthreads();
    }

    // ---------------- Phase C: trilinear gather (MLP=8) + exp cost ----------
    if (act) {
        float fr[3];
        int l0[3];
        bool valid = true;
        #pragma unroll
        for (int d = 0; d < 3; ++d) {
            float grid = (pv[d] - s_lo[d]) / 0.2f;
            float gp = 2.0f * grid / (float)(s_gls[d] - 1) - 1.0f;
            valid = valid && (gp < 0.99f) && (gp > -0.99f);
            float fl = floorf(grid);
            l0[d] = (int)fl;
            fr[d] = grid - fl;
        }

        // separable in-bounds -> fold into per-axis weights (exactly
        // reproduces where(inb, w*val, 0): zero weight kills the term)
        float wx0 = (l0[0] >= 0 && l0[0] < s_gls[0])         ? 1.0f - fr[0] : 0.0f;
        float wx1 = (l0[0] + 1 >= 0 && l0[0] + 1 < s_gls[0]) ? fr[0]        : 0.0f;
        float wy0 = (l0[1] >= 0 && l0[1] < s_gls[1])         ? 1.0f - fr[1] : 0.0f;
        float wy1 = (l0[1] + 1 >= 0 && l0[1] + 1 < s_gls[1]) ? fr[1]        : 0.0f;
        float wz0 = (l0[2] >= 0 && l0[2] < s_gls[2])         ? 1.0f - fr[2] : 0.0f;
        float wz1 = (l0[2] + 1 >= 0 && l0[2] + 1 < s_gls[2]) ? fr[2]        : 0.0f;

        int x0 = min(max(l0[0] + s_gmn[0], 0), NX - 1);
        int x1 = min(max(l0[0] + 1 + s_gmn[0], 0), NX - 1);
        int y0 = min(max(l0[1] + s_gmn[1], 0), NY - 1);
        int y1 = min(max(l0[1] + 1 + s_gmn[1], 0), NY - 1);
        int z0 = min(max(l0[2] + s_gmn[2], 0), NZ - 1);
        int z1 = min(max(l0[2] + 1 + s_gmn[2], 0), NZ - 1);

        int base = s_m * (NZ * NY * NX);       // fits in int32 (41M max)
        int r00 = base + z0 * (NY * NX) + y0 * NX;
        int r01 = base + z1 * (NY * NX) + y0 * NX;
        int r10 = base + z0 * (NY * NX) + y1 * NX;
        int r11 = base + z1 * (NY * NX) + y1 * NX;

        // all 8 loads issued back-to-back: single latency exposure
        float v000 = __ldg(sdf + r00 + x0);
        float v001 = __ldg(sdf + r01 + x0);
        float v010 = __ldg(sdf + r10 + x0);
        float v011 = __ldg(sdf + r11 + x0);
        float v100 = __ldg(sdf + r00 + x1);
        float v101 = __ldg(sdf + r01 + x1);
        float v110 = __ldg(sdf + r10 + x1);
        float v111 = __ldg(sdf + r11 + x1);

        float acc =
            wx0 * (wy0 * (wz0 * v000 + wz1 * v001) +
                   wy1 * (wz0 * v010 + wz1 * v011)) +
            wx1 * (wy0 * (wz0 * v100 + wz1 * v101) +
                   wy1 * (wz0 * v110 + wz1 * v111));

        float cost = valid ? __expf((-(acc - 0.5f)) / 0.3f) : 0.0f;
        const float dtf = (float)(2.0 / 30.0);
        s_cost[tid] = cost * dtf;
    }
    __syncthreads();

    if (tid < TRAJ) {
        float s = 0.0f;
        #pragma unroll
        for (int n = 0; n < EVALN; ++n)
            s += s_cost[tid * EVALN + n];
        out[g * TRAJ + tid] = s;
    }
}

// ---------------------------------------------------------------------------
extern "C" void kernel_launch(void* const* d_in, const int* in_sizes, int n_in,
                              void* d_out, int out_size)
{
    const float* Df     = (const float*)d_in[0];
    const float* Dp     = (const float*)d_in[1];
    const float* L      = (const float*)d_in[2];
    const float* sdf    = (const float*)d_in[3];
    const float* minb   = (const float*)d_in[4];
    const float* shapes = (const float*)d_in[5];
    const int*   map_id = (const int*)d_in[6];
    float* out = (float*)d_out;

    k_fused<<<G_GROUPS, 256>>>(Df, Dp, L, sdf, minb, shapes, map_id, out);
}